// round 2
// baseline (speedup 1.0000x reference)
#include <cuda_runtime.h>
#include <cstdint>

// Problem constants
#define NB    32
#define CIN   64
#define COUT  128
#define HDIM  128
#define WDIM  128
#define KK    3
#define NGRP  8
#define EPS   1e-5f

// Transposed weight scratch: Wt[kh][kw][ic][oc], tf32-rounded fp32 bits
__device__ float g_wt[KK * KK * CIN * COUT];

// ---------------------------------------------------------------------------
// Weight transform: w (Cin, Cout, 3, 3) -> Wt[kh][kw][ic][oc], cvt.rna to tf32
// ---------------------------------------------------------------------------
__global__ void wt_transform_kernel(const float* __restrict__ w) {
    int d = blockIdx.x * blockDim.x + threadIdx.x;
    if (d >= KK * KK * CIN * COUT) return;
    int oc  = d & (COUT - 1);
    int ic  = (d >> 7) & (CIN - 1);
    int kwh = d >> 13;            // 0..8
    int kh  = kwh / 3;
    int kw  = kwh - kh * 3;
    float v = w[((ic * COUT + oc) * KK + kh) * KK + kw];
    uint32_t r;
    asm("cvt.rna.tf32.f32 %0, %1;" : "=r"(r) : "f"(v));
    g_wt[d] = __uint_as_float(r);
}

// ---------------------------------------------------------------------------
// Helpers
// ---------------------------------------------------------------------------
__device__ __forceinline__ uint32_t f2tf32(float f) {
    uint32_t r;
    asm("cvt.rna.tf32.f32 %0, %1;" : "=r"(r) : "f"(f));
    return r;
}

__device__ __forceinline__ void cp_async16(uint32_t saddr, const void* gaddr, bool pred) {
    int sz = pred ? 16 : 0;  // src-size 0 => zero-fill (ZFILL)
    asm volatile("cp.async.cg.shared.global [%0], [%1], 16, %2;\n"
                 :: "r"(saddr), "l"(gaddr), "r"(sz));
}

__device__ __forceinline__ float gelu_tanh(float y) {
    float u = 0.7978845608f * (y + 0.044715f * y * y * y);
    float e = __expf(2.0f * u);
    float th = 1.0f - __fdividef(2.0f, e + 1.0f);  // tanh(u), stable at +/-inf
    return 0.5f * y * (1.0f + th);
}

__device__ __forceinline__ void mma_tf32(float& d0, float& d1, float& d2, float& d3,
                                         uint32_t a0, uint32_t a1, uint32_t a2, uint32_t a3,
                                         uint32_t b0, uint32_t b1) {
    asm volatile(
        "mma.sync.aligned.m16n8k8.row.col.f32.tf32.tf32.f32 "
        "{%0,%1,%2,%3}, {%4,%5,%6,%7}, {%8,%9}, {%0,%1,%2,%3};\n"
        : "+f"(d0), "+f"(d1), "+f"(d2), "+f"(d3)
        : "r"(a0), "r"(a1), "r"(a2), "r"(a3), "r"(b0), "r"(b1));
}

// Shared memory layout (floats), per buffer:
//   Xs: 2 rows-sets x 16 ic x 136  (x data at j=4..131, zeros at j=0..3)
//   Ws: 3 kw x 16 ic x 136         (weights at j=0..127)
#define XROW       136
#define XS_FLOATS  (2 * 16 * XROW)         // 4352
#define WS_FLOATS  (3 * 16 * XROW)         // 6528
#define STAGE_FLOATS (XS_FLOATS + WS_FLOATS) // 10880
#define SMEM_BYTES (2 * STAGE_FLOATS * 4)  // 87040

// ---------------------------------------------------------------------------
// Fused conv-transpose (cropped) + GELU + per-pixel GroupNorm
// CTA: 2 pixel rows (M=256) x 128 channels, 8 warps (4 m x 2 n), warp 64x64
// ---------------------------------------------------------------------------
__global__ void __launch_bounds__(256, 1)
fused_kernel(const float* __restrict__ x,
             const float* __restrict__ bias,
             const float* __restrict__ gamma,
             const float* __restrict__ beta,
             float* __restrict__ out) {
    extern __shared__ float smem[];
    const int tid  = threadIdx.x;
    const int nimg = blockIdx.y;
    const int r0   = blockIdx.x * 2;

    const uint32_t smem_u = (uint32_t)__cvta_generic_to_shared(smem);

    // Zero the left-pad columns (j=0..3) of Xs in both buffers (written once;
    // cp.async only writes j>=4).
    {
        int b   = tid >> 7;
        int rem = tid & 127;
        int prs = rem >> 6;
        int pi  = (rem >> 2) & 15;
        int pj  = rem & 3;
        smem[b * STAGE_FLOATS + (prs * 16 + pi) * XROW + pj] = 0.0f;
    }

    const int lane = tid & 31;
    const int warp = tid >> 5;
    const int g    = lane >> 2;   // groupID
    const int t    = lane & 3;    // threadID in group
    const int wm   = warp & 3;    // m-warp index (0..3)
    const int wn   = warp >> 2;   // n-warp index (0..1)
    const int rs   = wm >> 1;     // which of the two pixel rows this warp owns
    const int mcol = (wm & 1) * 64;
    const int nb   = wn * 64;

    // stage loader: stage s = kh*4 + icc, into buffer buf
    auto issue_stage = [&](int s, int buf) {
        const int kh  = s >> 2;
        const int icc = s & 3;
        const uint32_t base = smem_u + (uint32_t)(buf * STAGE_FLOATS * 4);
        // Xs: 1024 x 16B chunks
        #pragma unroll
        for (int it = 0; it < 4; ++it) {
            int idx = tid + it * 256;
            int prs = idx >> 9;
            int i   = (idx >> 5) & 15;
            int c   = idx & 31;
            int ih  = r0 + prs - kh;
            bool ok = (ih >= 0);
            int ihc = ok ? ih : 0;
            int ic  = icc * 16 + i;
            const float* gp = x + ((((nimg * CIN + ic) * HDIM + ihc) << 7) + c * 4);
            uint32_t sa = base + (uint32_t)(((prs * 16 + i) * XROW + 4 + c * 4) * 4);
            cp_async16(sa, gp, ok);
        }
        // Ws: 1536 x 16B chunks
        #pragma unroll
        for (int it = 0; it < 6; ++it) {
            int idx = tid + it * 256;
            int kw  = idx >> 9;
            int i   = (idx >> 5) & 15;
            int c   = idx & 31;
            const float* gp = g_wt + ((((kh * 3 + kw) * CIN + icc * 16 + i) << 7) + c * 4);
            uint32_t sa = base + (uint32_t)((XS_FLOATS + (kw * 16 + i) * XROW + c * 4) * 4);
            cp_async16(sa, gp, true);
        }
        asm volatile("cp.async.commit_group;\n");
    };

    float acc[4][8][4];
    #pragma unroll
    for (int mt = 0; mt < 4; ++mt)
        #pragma unroll
        for (int nt = 0; nt < 8; ++nt)
            #pragma unroll
            for (int q = 0; q < 4; ++q) acc[mt][nt][q] = 0.0f;

    issue_stage(0, 0);

    for (int s = 0; s < 12; ++s) {
        if (s + 1 < 12) {
            issue_stage(s + 1, (s + 1) & 1);
            asm volatile("cp.async.wait_group 1;\n");
        } else {
            asm volatile("cp.async.wait_group 0;\n");
        }
        __syncthreads();

        const float* Xs = smem + (s & 1) * STAGE_FLOATS + rs * 16 * XROW;
        const float* Ws = smem + (s & 1) * STAGE_FLOATS + XS_FLOATS;

        #pragma unroll
        for (int kw = 0; kw < 3; ++kw) {
            const int jb = mcol + 4 - kw + g;           // x col index base (padded)
            const float* Wp = Ws + kw * 16 * XROW + nb + g;
            #pragma unroll
            for (int ks = 0; ks < 2; ++ks) {
                const int kr = ks * 8 + t;
                // A fragments (cvt.rna to tf32 after LDS; smem holds raw fp32 x)
                uint32_t a[4][4];
                #pragma unroll
                for (int mt = 0; mt < 4; ++mt) {
                    int jj = jb + mt * 16;
                    a[mt][0] = f2tf32(Xs[kr * XROW + jj]);
                    a[mt][1] = f2tf32(Xs[kr * XROW + jj + 8]);
                    a[mt][2] = f2tf32(Xs[(kr + 4) * XROW + jj]);
                    a[mt][3] = f2tf32(Xs[(kr + 4) * XROW + jj + 8]);
                }
                // B fragments (already tf32 bits)
                uint32_t b2[8][2];
                #pragma unroll
                for (int nt = 0; nt < 8; ++nt) {
                    b2[nt][0] = __float_as_uint(Wp[kr * XROW + nt * 8]);
                    b2[nt][1] = __float_as_uint(Wp[(kr + 4) * XROW + nt * 8]);
                }
                #pragma unroll
                for (int mt = 0; mt < 4; ++mt)
                    #pragma unroll
                    for (int nt = 0; nt < 8; ++nt)
                        mma_tf32(acc[mt][nt][0], acc[mt][nt][1], acc[mt][nt][2], acc[mt][nt][3],
                                 a[mt][0], a[mt][1], a[mt][2], a[mt][3],
                                 b2[nt][0], b2[nt][1]);
            }
        }
        __syncthreads();
    }

    // ---------------- Epilogue: bias + GELU + per-pixel GroupNorm ----------
    // Each thread owns 16 fixed channels: oc(q) = nb + nt*8 + 2t + j, q = 2nt+j
    float b_r[16], ga[16], be[16];
    #pragma unroll
    for (int nt = 0; nt < 8; ++nt)
        #pragma unroll
        for (int j = 0; j < 2; ++j) {
            int q  = nt * 2 + j;
            int oc = nb + nt * 8 + 2 * t + j;
            b_r[q] = __ldg(bias + oc);
            ga[q]  = __ldg(gamma + oc);
            be[q]  = __ldg(beta + oc);
        }

    const int oh = r0 + rs;
    const long out_img = (long)nimg * COUT * HDIM * WDIM;

    #pragma unroll
    for (int mt = 0; mt < 4; ++mt) {
        #pragma unroll
        for (int h = 0; h < 2; ++h) {
            int ow = mcol + mt * 16 + g + 8 * h;
            float gv[16];
            #pragma unroll
            for (int nt = 0; nt < 8; ++nt)
                #pragma unroll
                for (int j = 0; j < 2; ++j) {
                    int q = nt * 2 + j;
                    float y = acc[mt][nt][2 * h + j] + b_r[q];
                    gv[q] = gelu_tanh(y);
                }
            // 4 groups of 16 channels per warp-half; each group lives in one quad
            #pragma unroll
            for (int g2 = 0; g2 < 4; ++g2) {
                float s1 = gv[4 * g2] + gv[4 * g2 + 1] + gv[4 * g2 + 2] + gv[4 * g2 + 3];
                float s2 = gv[4 * g2] * gv[4 * g2] + gv[4 * g2 + 1] * gv[4 * g2 + 1] +
                           gv[4 * g2 + 2] * gv[4 * g2 + 2] + gv[4 * g2 + 3] * gv[4 * g2 + 3];
                s1 += __shfl_xor_sync(0xffffffffu, s1, 1);
                s2 += __shfl_xor_sync(0xffffffffu, s2, 1);
                s1 += __shfl_xor_sync(0xffffffffu, s1, 2);
                s2 += __shfl_xor_sync(0xffffffffu, s2, 2);
                float mean = s1 * (1.0f / 16.0f);
                float var  = s2 * (1.0f / 16.0f) - mean * mean;
                float rstd = rsqrtf(var + EPS);
                #pragma unroll
                for (int u = 0; u < 4; ++u) {
                    int q  = 4 * g2 + u;
                    int nt = q >> 1;
                    int j  = q & 1;
                    int oc = nb + nt * 8 + 2 * t + j;
                    float val = (gv[q] - mean) * rstd * ga[q] + be[q];
                    out[out_img + (long)oc * (HDIM * WDIM) + oh * WDIM + ow] = val;
                }
            }
        }
    }
}

// ---------------------------------------------------------------------------
// Launch
// ---------------------------------------------------------------------------
extern "C" void kernel_launch(void* const* d_in, const int* in_sizes, int n_in,
                              void* d_out, int out_size) {
    const float* x  = (const float*)d_in[0];
    const float* w  = (const float*)d_in[1];
    const float* b  = (const float*)d_in[2];
    const float* gw = (const float*)d_in[3];
    const float* gb = (const float*)d_in[4];
    float* out = (float*)d_out;

    // One-time-per-launch weight re-layout (deterministic, graph-capturable)
    wt_transform_kernel<<<(KK * KK * CIN * COUT + 255) / 256, 256>>>(w);

    cudaFuncSetAttribute(fused_kernel,
                         cudaFuncAttributeMaxDynamicSharedMemorySize, SMEM_BYTES);
    dim3 grid(HDIM / 2, NB);  // 64 x 32 = 2048 CTAs
    fused_kernel<<<grid, 256, SMEM_BYTES>>>(x, b, gw, gb, out);
}